// round 16
// baseline (speedup 1.0000x reference)
#include <cuda_runtime.h>
#include <cuda_bf16.h>
#include <cstdint>

#define NN 100000
#define EE 1600000
#define DD 128
#define GG 64
#define NB2 148          // gemm2 blocks

#define A_ST 68          // gemm1 A tile stride (f16x2 words)
#define W_ST 136         // gemm1 W tile stride (f16x2 words)
#define ST_W 65
#define ST_X 66

// ---------------- device scratch ----------------
__device__ float    g_agg[(size_t)NN * DD];      // spmm1 output (fp32)
__device__ unsigned g_xh[(size_t)NN * DD / 2];   // bf16x2 scaled input features
__device__ unsigned g_xh2[(size_t)NN * DD / 2];  // bf16x2 layer-1 output
__device__ float    g_w[(size_t)NN * GG];        // per-(src,graph) pooling weights
__device__ unsigned g_w1h[DD / 2 * DD];          // W1 packed f16x2 along k: [k/2][n]
__device__ float    g_pool[GG * DD];             // pooled sums (red target)
__device__ uint2    g_gd[NN];                    // packed {gid, ndst}
__device__ int      g_deg[2 * NN];               // [0,NN)=deg_out, [NN,2NN)=deg_in
__device__ float    g_nsrc[NN];
__device__ float    g_ndst[NN];
__device__ float    g_cnt[GG];
__device__ int      g_off[NN];
__device__ int      g_cursor[NN];
__device__ int      g_sorted[EE];
__device__ int      g_counter;

// ---------------- helpers ----------------
__device__ __forceinline__ unsigned f2tf32(float x) {
    unsigned r;
    asm("cvt.rna.tf32.f32 %0, %1;" : "=r"(r) : "f"(x));
    return r;
}
__device__ __forceinline__ unsigned pack_bf16x2(float lo, float hi) {
    unsigned r;
    asm("cvt.rn.bf16x2.f32 %0, %1, %2;" : "=r"(r) : "f"(hi), "f"(lo));
    return r;
}
__device__ __forceinline__ unsigned pack_f16x2(float lo, float hi) {
    unsigned r;
    asm("cvt.rn.f16x2.f32 %0, %1, %2;" : "=r"(r) : "f"(hi), "f"(lo));
    return r;
}
__device__ __forceinline__ void mma_tf32(float& d0, float& d1, float& d2, float& d3,
                                         unsigned a0, unsigned a1, unsigned a2, unsigned a3,
                                         unsigned b0, unsigned b1) {
    asm("mma.sync.aligned.m16n8k8.row.col.f32.tf32.tf32.f32 "
        "{%0,%1,%2,%3}, {%4,%5,%6,%7}, {%8,%9}, {%0,%1,%2,%3};"
        : "+f"(d0), "+f"(d1), "+f"(d2), "+f"(d3)
        : "r"(a0), "r"(a1), "r"(a2), "r"(a3), "r"(b0), "r"(b1));
}
__device__ __forceinline__ void mma_f16(float& d0, float& d1, float& d2, float& d3,
                                        unsigned a0, unsigned a1, unsigned a2, unsigned a3,
                                        unsigned b0, unsigned b1) {
    asm("mma.sync.aligned.m16n8k16.row.col.f32.f16.f16.f32 "
        "{%0,%1,%2,%3}, {%4,%5,%6,%7}, {%8,%9}, {%0,%1,%2,%3};"
        : "+f"(d0), "+f"(d1), "+f"(d2), "+f"(d3)
        : "r"(a0), "r"(a1), "r"(a2), "r"(a3), "r"(b0), "r"(b1));
}
__device__ __forceinline__ float bf_lo(unsigned u) { return __uint_as_float(u << 16); }
__device__ __forceinline__ float bf_hi(unsigned u) { return __uint_as_float(u & 0xffff0000u); }
__device__ __forceinline__ void acc_bf16(float4& a, uint2 u) {
    a.x += bf_lo(u.x); a.y += bf_hi(u.x);
    a.z += bf_lo(u.y); a.w += bf_hi(u.y);
}
__device__ __forceinline__ void red_v4(float* p, float4 v) {
    asm volatile("red.global.add.v4.f32 [%0], {%1,%2,%3,%4};"
                 :: "l"(p), "f"(v.x), "f"(v.y), "f"(v.z), "f"(v.w) : "memory");
}

// ---------------- launch 1: degree count + zero w/pool/cnt/counter ----------------
__global__ void k_degree(const int* __restrict__ src, const int* __restrict__ dst, int E) {
    int i0 = blockIdx.x * blockDim.x + threadIdx.x;
    int stride = gridDim.x * blockDim.x;
    float4 z = make_float4(0.f, 0.f, 0.f, 0.f);
    for (int i = i0; i < NN * GG / 4; i += stride) ((float4*)g_w)[i] = z;
    for (int i = i0; i < GG * DD; i += stride) g_pool[i] = 0.f;
    if (i0 < GG) g_cnt[i0] = 0.f;
    if (i0 == GG) g_counter = 0;
    for (int i = i0; i < E; i += stride) {
        atomicAdd(&g_deg[src[i]], 1);
        atomicAdd(&g_deg[NN + dst[i]], 1);
    }
}

// ---------------- launch 2: norms, gd pack, counts, offsets (warp-aggregated) + W1->f16x2 ----------------
__global__ void k_nodeprep(const int* __restrict__ gid, const float* __restrict__ W1, int N) {
    int i = blockIdx.x * blockDim.x + threadIdx.x;
    int lane = threadIdx.x & 31;
    if (i < DD / 2 * DD) {
        int m = i >> 7;            // k-pair index
        int n = i & 127;
        g_w1h[i] = pack_f16x2(W1[(2 * m) * DD + n], W1[(2 * m + 1) * DD + n]);
    }
    // warp-aggregated segment-offset assignment: ONE atomic per warp
    int din = (i < N) ? g_deg[NN + i] : 0;
    int scan = din;
#pragma unroll
    for (int o = 1; o < 32; o <<= 1) {
        int v = __shfl_up_sync(0xffffffffu, scan, o);
        if (lane >= o) scan += v;
    }
    int total = __shfl_sync(0xffffffffu, scan, 31);   // warp sum
    int base = 0;
    if (lane == 0 && total > 0) base = atomicAdd(&g_counter, total);
    base = __shfl_sync(0xffffffffu, base, 0);
    if (i < N) {
        int off = base + scan - din;     // exclusive within warp
        g_off[i] = off;
        g_cursor[i] = off;
        int dout = g_deg[i];
        float ns = rsqrtf((float)max(dout, 1));
        float nd = rsqrtf((float)max(din, 1));
        g_nsrc[i] = ns;
        g_ndst[i] = nd;
        int g = gid[i];
        g_gd[i] = make_uint2((unsigned)g, __float_as_uint(nd));
        atomicAdd(&g_cnt[g], 1.f);
    }
}

// ---------------- launch 3: scatter + wbuild (edges) and bf16 prep (nodes) ----------------
__global__ void k_edge_node(const int* __restrict__ src, const int* __restrict__ dst,
                            const float* __restrict__ x, int E, int N) {
    int i = blockIdx.x * blockDim.x + threadIdx.x;
    if (i < E) {
        int s = src[i];
        int d = dst[i];
        int p = atomicAdd(&g_cursor[d], 1);
        g_sorted[p] = s;
        uint2 gd = g_gd[d];
        atomicAdd(&g_w[(size_t)s * GG + gd.x], __uint_as_float(gd.y));
    } else {
        int j = i - E;                       // float4 index over node features
        if (j < N * 32) {
            int n = j >> 5;
            float sc = g_nsrc[n];
            float4 v = ((const float4*)x)[j];
            uint2 u;
            u.x = pack_bf16x2(v.x * sc, v.y * sc);
            u.y = pack_bf16x2(v.z * sc, v.w * sc);
            ((uint2*)g_xh)[j] = u;
        }
    }
}

// ---------------- launch 4 (PROFILED): SpMM layer 1 ----------------
__global__ void __launch_bounds__(256) k_spmm1(int N) {
    int warp = (blockIdx.x * blockDim.x + threadIdx.x) >> 5;
    if (warp >= N) return;
    int lane = threadIdx.x & 31;
    const uint2* xh = (const uint2*)g_xh;
    int e0 = g_off[warp];
    int e1 = e0 + g_deg[NN + warp];
    float4 acc = make_float4(0.f, 0.f, 0.f, 0.f);
    for (int base = e0; base < e1; base += 32) {
        int nrem = e1 - base;
        int idx = (lane < nrem) ? g_sorted[base + lane] : 0;
        int m = min(32, nrem);
        int j = 0;
        for (; j + 8 <= m; j += 8) {
            uint2 u[8];
#pragma unroll
            for (int q = 0; q < 8; q++) {
                int s = __shfl_sync(0xffffffffu, idx, j + q);
                u[q] = xh[(size_t)s * 32 + lane];
            }
#pragma unroll
            for (int q = 0; q < 8; q++) acc_bf16(acc, u[q]);
        }
        for (; j < m; j++) {
            int s = __shfl_sync(0xffffffffu, idx, j);
            acc_bf16(acc, xh[(size_t)s * 32 + lane]);
        }
    }
    *(float4*)(g_agg + (size_t)warp * DD + lane * 4) = acc;
}

// ---------------- launch 5: dense stage 1 (fp16 m16n8k16 MMA) ----------------
__global__ void __launch_bounds__(256) k_gemm1(const float* __restrict__ b, int N) {
    __shared__ unsigned sA[64 * A_ST];   // f16x2 words: [row][k/2]
    __shared__ unsigned sW[64 * W_ST];   // f16x2 words: [k/2][n]

    int t = threadIdx.x;
    int row0 = blockIdx.x * 64;
    int wid = t >> 5;
    int lane = t & 31;

#pragma unroll
    for (int i = 0; i < 8; i++) {
        int q = t + i * 256;
        int r = q >> 5;
        int c = q & 31;
        uint4 v = ((const uint4*)g_w1h)[q];
        *(uint4*)(sW + r * W_ST + c * 4) = v;
    }
#pragma unroll
    for (int i = 0; i < 16; i++) {
        int q = t + i * 256;
        int r = q >> 6;
        int c = q & 63;
        int row = row0 + r;
        unsigned o = 0u;
        if (row < N) {
            float2 v = *(const float2*)(g_agg + (size_t)row * DD + c * 2);
            float s = g_ndst[row];
            o = pack_f16x2(v.x * s, v.y * s);
        }
        sA[r * A_ST + c] = o;
    }
    __syncthreads();

    int g = lane >> 2;
    int tg = lane & 3;
    int wm = wid >> 2;
    int wn = wid & 3;

    float acc[2][4][4];
#pragma unroll
    for (int i = 0; i < 2; i++)
#pragma unroll
        for (int j = 0; j < 4; j++)
#pragma unroll
            for (int q = 0; q < 4; q++) acc[i][j][q] = 0.f;

#pragma unroll
    for (int ks = 0; ks < 8; ks++) {
        int kw = ks * 8;
        unsigned a[2][4];
#pragma unroll
        for (int i = 0; i < 2; i++) {
            int rA = (wm * 32 + i * 16 + g) * A_ST + kw;
            int rB = (wm * 32 + i * 16 + g + 8) * A_ST + kw;
            a[i][0] = sA[rA + tg];
            a[i][1] = sA[rB + tg];
            a[i][2] = sA[rA + tg + 4];
            a[i][3] = sA[rB + tg + 4];
        }
        unsigned bb[4][2];
#pragma unroll
        for (int j = 0; j < 4; j++) {
            int n = wn * 32 + j * 8 + g;
            bb[j][0] = sW[(kw + tg) * W_ST + n];
            bb[j][1] = sW[(kw + tg + 4) * W_ST + n];
        }
#pragma unroll
        for (int i = 0; i < 2; i++)
#pragma unroll
            for (int j = 0; j < 4; j++)
                mma_f16(acc[i][j][0], acc[i][j][1], acc[i][j][2], acc[i][j][3],
                        a[i][0], a[i][1], a[i][2], a[i][3], bb[j][0], bb[j][1]);
    }

#pragma unroll
    for (int i = 0; i < 2; i++) {
        int rA = row0 + wm * 32 + i * 16 + g;
        int rB = rA + 8;
        float sA_ = (rA < N) ? g_nsrc[rA] : 0.f;
        float sB_ = (rB < N) ? g_nsrc[rB] : 0.f;
#pragma unroll
        for (int j = 0; j < 4; j++) {
            int c = wn * 32 + j * 8 + tg * 2;
            float bx = b[c], by = b[c + 1];
            if (rA < N) {
                float x0 = fmaxf(acc[i][j][0] + bx, 0.f) * sA_;
                float x1 = fmaxf(acc[i][j][1] + by, 0.f) * sA_;
                g_xh2[(size_t)rA * 64 + (c >> 1)] = pack_bf16x2(x0, x1);
            }
            if (rB < N) {
                float x2 = fmaxf(acc[i][j][2] + bx, 0.f) * sB_;
                float x3 = fmaxf(acc[i][j][3] + by, 0.f) * sB_;
                g_xh2[(size_t)rB * 64 + (c >> 1)] = pack_bf16x2(x2, x3);
            }
        }
    }
}

// ---------------- launch 6: gemm2 (tf32 MMA, K-chunk=64 nodes) ----------------
#define G2_K 64
__global__ void __launch_bounds__(256) k_gemm2(int N) {
    __shared__ float smem_raw[G2_K * ST_W + G2_K * ST_X];  // 33.5KB
    float*    sw = smem_raw;                    // [k][g]
    unsigned* sx = (unsigned*)(smem_raw + G2_K * ST_W);  // [k][word]
    float*    spool = smem_raw;                 // overlay for output staging

    int t = threadIdx.x;
    int wid = t >> 5;
    int lane = t & 31;
    int g = lane >> 2;
    int tg = lane & 3;
    int wm = wid >> 1;
    int wn = wid & 1;

    int chunk = (N + NB2 - 1) / NB2;
    int nb0 = blockIdx.x * chunk;
    int nend = min(nb0 + chunk, N);

    float acc[8][4];
#pragma unroll
    for (int j = 0; j < 8; j++)
#pragma unroll
        for (int q = 0; q < 4; q++) acc[j][q] = 0.f;

    for (int nb = nb0; nb < nend; nb += G2_K) {
#pragma unroll
        for (int i = 0; i < 16; i++) {
            int word = t + i * 256;
            int k = word >> 6, col = word & 63;
            int n = nb + k;
            bool ok = (n < nend);
            sw[k * ST_W + col] = ok ? g_w[(size_t)n * GG + col] : 0.f;
            sx[k * ST_X + col] = ok ? g_xh2[(size_t)n * 64 + col] : 0u;
        }
        __syncthreads();

#pragma unroll
        for (int ks = 0; ks < G2_K / 8; ks++) {
            int k0 = ks * 8;
            unsigned a0 = f2tf32(sw[(k0 + tg) * ST_W + wm * 16 + g]);
            unsigned a1 = f2tf32(sw[(k0 + tg) * ST_W + wm * 16 + g + 8]);
            unsigned a2 = f2tf32(sw[(k0 + tg + 4) * ST_W + wm * 16 + g]);
            unsigned a3 = f2tf32(sw[(k0 + tg + 4) * ST_W + wm * 16 + g + 8]);
#pragma unroll
            for (int j = 0; j < 8; j++) {
                int nj = wn * 64 + j * 8;
                int wrd = (nj >> 1) + (g >> 1);
                unsigned u0 = sx[(k0 + tg) * ST_X + wrd];
                unsigned u1 = sx[(k0 + tg + 4) * ST_X + wrd];
                unsigned b0 = (g & 1) ? (u0 & 0xffff0000u) : (u0 << 16);
                unsigned b1 = (g & 1) ? (u1 & 0xffff0000u) : (u1 << 16);
                mma_tf32(acc[j][0], acc[j][1], acc[j][2], acc[j][3],
                         a0, a1, a2, a3, b0, b1);
            }
        }
        __syncthreads();
    }

#pragma unroll
    for (int j = 0; j < 8; j++) {
        int nj = wn * 64 + j * 8 + tg * 2;
        int r = wm * 16 + g;
        spool[r * DD + nj] = acc[j][0];
        spool[r * DD + nj + 1] = acc[j][1];
        spool[(r + 8) * DD + nj] = acc[j][2];
        spool[(r + 8) * DD + nj + 1] = acc[j][3];
    }
    __syncthreads();
#pragma unroll
    for (int i = 0; i < 8; i++) {
        int q = t + i * 256;
        float4 v = ((float4*)spool)[q];
        red_v4(g_pool + q * 4, v);
    }
}

// ---------------- launch 7: out = (g_pool/cnt) @ W2 + b2 ----------------
__global__ void k_final(const float* __restrict__ W2, const float* __restrict__ b2,
                        float* __restrict__ out) {
    __shared__ float srow[DD];
    int g = blockIdx.x, t = threadIdx.x;
    srow[t] = g_pool[g * DD + t] / fmaxf(g_cnt[g], 1.f);
    __syncthreads();
    float a = b2[t];
#pragma unroll 8
    for (int k = 0; k < DD; k++) a += srow[k] * W2[k * DD + t];
    out[g * DD + t] = a;
}

// ---------------- launch ----------------
extern "C" void kernel_launch(void* const* d_in, const int* in_sizes, int n_in,
                              void* d_out, int out_size) {
    const float* in_feat = (const float*)d_in[0];
    const float* W1 = (const float*)d_in[1];
    const float* b1 = (const float*)d_in[2];
    const float* W2 = (const float*)d_in[3];
    const float* b2 = (const float*)d_in[4];
    const int* src = (const int*)d_in[5];
    const int* dst = (const int*)d_in[6];
    const int* gid = (const int*)d_in[7];
    int N = in_sizes[0] / DD;
    int E = in_sizes[5];
    (void)n_in; (void)out_size;

    void* p_deg;
    cudaGetSymbolAddress(&p_deg, g_deg);

    cudaMemsetAsync(p_deg, 0, 2 * NN * sizeof(int));

    k_degree<<<1024, 256>>>(src, dst, E);                                     // 1
    k_nodeprep<<<(N + 255) / 256, 256>>>(gid, W1, N);                         // 2
    k_edge_node<<<(E + N * 32 + 255) / 256, 256>>>(src, dst, in_feat, E, N);  // 3
    k_spmm1<<<(N + 7) / 8, 256>>>(N);                                         // 4 <- profiled
    k_gemm1<<<(N + 63) / 64, 256>>>(b1, N);                                   // 5
    k_gemm2<<<NB2, 256>>>(N);                                                 // 6
    k_final<<<GG, DD>>>(W2, b2, (float*)d_out);                               // 7
}